// round 10
// baseline (speedup 1.0000x reference)
#include <cuda_runtime.h>

#define BB 4
#define CC 17
#define TT 75000
#define HH 32
#define NTHREADS 256
#define TILE 8192
#define NTILE 10          // ceil(75000/8192)
#define MAXPART 256

#define NTILEBLK (18 * NTILE * HH * BB)   // 23040
#define NRESBLK  15872

// Deterministic partial accumulation scratch: [combo 28][b 4][h 32][part 256][16]
__device__ float g_partial[28][4][32][MAXPART][16];

typedef unsigned long long ull;

// ---------------- f32x2 helpers ----------------
__device__ __forceinline__ ull pack2(float a, float b) {
    ull r; asm("mov.b64 %0, {%1, %2};" : "=l"(r) : "f"(a), "f"(b)); return r;
}
__device__ __forceinline__ ull dup2(float a) {
    ull r; asm("mov.b64 %0, {%1, %1};" : "=l"(r) : "f"(a)); return r;
}
__device__ __forceinline__ void mul2(ull& z, ull a, ull b) {
    asm("mul.rn.f32x2 %0, %1, %2;" : "=l"(z) : "l"(a), "l"(b));
}
__device__ __forceinline__ void fma2(ull& z, ull a, ull b) {
    asm("fma.rn.f32x2 %0, %1, %2, %0;" : "+l"(z) : "l"(a), "l"(b));
}
__device__ __forceinline__ void unpack2(ull z, float& lo, float& hi) {
    asm("mov.b64 {%0, %1}, %2;" : "=f"(lo), "=f"(hi) : "l"(z));
}

// ---------------- scalar minmax + bucket ----------------
__device__ __forceinline__ void bucket(const float z[8], float am[8], float an[8],
                                       float vf) {
    float mx = fmaxf(fmaxf(fmaxf(z[0], z[1]), fmaxf(z[2], z[3])),
                     fmaxf(fmaxf(z[4], z[5]), fmaxf(z[6], z[7])));
    float mn = fminf(fminf(fminf(z[0], z[1]), fminf(z[2], z[3])),
                     fminf(fminf(z[4], z[5]), fminf(z[6], z[7])));
#pragma unroll
    for (int k = 0; k < 8; k++) {
        if (z[k] == mx) am[k] += z[k];   // z==0 for invalid pos -> adds 0
        if (z[k] == mn) an[k] += vf;     // masked by validity
    }
}

// k-packed conv step (residue path): gd = 9 dup'd {g,g}, ROT compile-time.
// w2[kk][j] = { w[2kk][j], w[2kk+1][j] }
template <int ROT>
__device__ __forceinline__ void conv_step(const ull gd[9], const ull w2[4][9],
                                          float am[8], float an[8]) {
    ull acc[4];
    {
        ull g2 = gd[ROT % 9];
#pragma unroll
        for (int kk = 0; kk < 4; kk++) mul2(acc[kk], g2, w2[kk][0]);
    }
#pragma unroll
    for (int j = 1; j < 9; j++) {
        ull g2 = gd[(ROT + j) % 9];
#pragma unroll
        for (int kk = 0; kk < 4; kk++) fma2(acc[kk], g2, w2[kk][j]);
    }
    float z[8];
#pragma unroll
    for (int kk = 0; kk < 4; kk++) unpack2(acc[kk], z[2 * kk], z[2 * kk + 1]);
    bucket(z, am, an, 1.0f);
}

// residue-path weights: k-paired
__device__ __forceinline__ void load_w2(const float* __restrict__ W, int ci, int h,
                                        ull w2[4][9]) {
    const float* wp = W + (ci * 256 + h * 8) * 9;
#pragma unroll
    for (int kk = 0; kk < 4; kk++)
#pragma unroll
        for (int j = 0; j < 9; j++)
            w2[kk][j] = pack2(__ldg(wp + (2 * kk) * 9 + j), __ldg(wp + (2 * kk + 1) * 9 + j));
}

// tile-path weights: duplicated {w,w} (positions in SIMD lanes)
__device__ __forceinline__ void load_wd(const float* __restrict__ W, int ci, int h,
                                        ull wd[8][9]) {
    const float* wp = W + (ci * 256 + h * 8) * 9;
#pragma unroll
    for (int k = 0; k < 8; k++)
#pragma unroll
        for (int j = 0; j < 9; j++)
            wd[k][j] = dup2(__ldg(wp + k * 9 + j));
}

__device__ __forceinline__ void block_write_partial(float* sw, float am[8], float an[8],
                                                    int ci, int b, int h, int blk) {
    int tid = threadIdx.x;
    int lane = tid & 31, warp = tid >> 5;
#pragma unroll
    for (int o = 0; o < 16; o++) {
        float v = (o < 8) ? am[o] : an[o - 8];
        v += __shfl_down_sync(0xffffffffu, v, 16);
        v += __shfl_down_sync(0xffffffffu, v, 8);
        v += __shfl_down_sync(0xffffffffu, v, 4);
        v += __shfl_down_sync(0xffffffffu, v, 2);
        v += __shfl_down_sync(0xffffffffu, v, 1);
        if (lane == 0) sw[warp * 16 + o] = v;
    }
    __syncthreads();
    if (tid < 16) {
        float s = 0.f;
#pragma unroll
        for (int wN = 0; wN < 8; wN++) s += sw[wN * 16 + tid];
        g_partial[ci][b][h][blk][tid] = s;
    }
}

// per-warp partial write (residue path, one h per warp)
__device__ __forceinline__ void warp_write_partial(float am[8], float an[8],
                                                   int ci, int b, int h, int part) {
    int lane = threadIdx.x & 31;
#pragma unroll
    for (int o = 0; o < 16; o++) {
        float v = (o < 8) ? am[o] : an[o - 8];
        v += __shfl_down_sync(0xffffffffu, v, 16);
        v += __shfl_down_sync(0xffffffffu, v, 8);
        v += __shfl_down_sync(0xffffffffu, v, 4);
        v += __shfl_down_sync(0xffffffffu, v, 2);
        v += __shfl_down_sync(0xffffffffu, v, 1);
        if (lane == 0) g_partial[ci][b][h][part][o] = v;
    }
}

// ============================================================================
// Position-paired conv, dup'd weights: one aligned LDS.64 {g_t+jD, g_t+jD+1}
// feeds all 8 k-accumulators; acc[k] = {z_t[k], z_u[k]}. No swap MOVs.
// ============================================================================
template <int DI>
__device__ __forceinline__ void pair_conv(const float* __restrict__ g_sh, int q,
                                          const ull wd[8][9],
                                          float am[8], float an[8],
                                          float vft, float vfu) {
    constexpr int D = 1 << DI;
    const ull* gp = (const ull*)g_sh;
    ull acc[8];

    if (DI == 0) {
        // window g[q .. q+9]; aligned pairs P[i] = {g[q+2i], g[q+2i+1]}
        ull P[5];
#pragma unroll
        for (int i = 0; i < 5; i++) P[i] = gp[(q >> 1) + i];
        float lo[5], hi[5];
#pragma unroll
        for (int i = 0; i < 5; i++) unpack2(P[i], lo[i], hi[i]);
#pragma unroll
        for (int j = 0; j < 9; j++) {
            ull v = ((j & 1) == 0) ? P[j >> 1]
                                   : pack2(hi[(j - 1) >> 1], lo[(j + 1) >> 1]);
            if (j == 0) {
#pragma unroll
                for (int k = 0; k < 8; k++) mul2(acc[k], v, wd[k][0]);
            } else {
#pragma unroll
                for (int k = 0; k < 8; k++) fma2(acc[k], v, wd[k][j]);
            }
        }
    } else {
#pragma unroll
        for (int j = 0; j < 9; j++) {
            ull v = gp[(q + j * D) >> 1];    // q even, j*D even -> aligned LDS.64
            if (j == 0) {
#pragma unroll
                for (int k = 0; k < 8; k++) mul2(acc[k], v, wd[k][0]);
            } else {
#pragma unroll
                for (int k = 0; k < 8; k++) fma2(acc[k], v, wd[k][j]);
            }
        }
    }

    float zt[8], zu[8];
#pragma unroll
    for (int k = 0; k < 8; k++) unpack2(acc[k], zt[k], zu[k]);
    bucket(zt, am, an, vft);
    bucket(zu, am, an, vfu);
}

// ============================================================================
// Tile path body: small dilation (di 0..8). Scalar g tile + paired conv.
// ============================================================================
template <int DI, int DIFF>
__device__ __forceinline__ void tile_body(int rlin, float* g_sh, float* sw,
                                          const float* __restrict__ X,
                                          const float* __restrict__ W,
                                          const int* __restrict__ idx) {
    constexpr int D = 1 << DI;
    constexpr int HALO = 4 * D;
    constexpr int N = TILE + 2 * HALO;
    constexpr int CI = DI * 2 + DIFF;
    constexpr int Te = TT - DIFF;

    int tile = rlin % NTILE;
    int h = (rlin / NTILE) % HH;
    int b = rlin / (NTILE * HH);
    int t0 = tile * TILE;
    int tid = threadIdx.x;

    int off[8];
    {
        const int* ip = idx + (CI * HH + h) * 8;
#pragma unroll
        for (int i = 0; i < 8; i++) off[i] = ip[i] * TT;
    }
    const float* Xb = X + b * CC * TT;

    // ---- build g tile (zero padded outside [0, Te)) ----
    if (DIFF == 0) {
        for (int i = 2 * tid; i < N; i += 2 * NTHREADS) {
            int t = t0 - HALO + i;
            float v0 = 0.f, v1 = 0.f;
            if (t >= 0 && t + 1 < TT) {
#pragma unroll
                for (int c = 0; c < 8; c++) {
                    float2 x = __ldg((const float2*)(Xb + off[c] + t));
                    v0 += x.x; v1 += x.y;
                }
            } else {
                if (t >= 0 && t < TT) {
#pragma unroll
                    for (int c = 0; c < 8; c++) v0 += __ldg(Xb + off[c] + t);
                }
                if (t + 1 >= 0 && t + 1 < TT) {
#pragma unroll
                    for (int c = 0; c < 8; c++) v1 += __ldg(Xb + off[c] + t + 1);
                }
            }
            g_sh[i] = v0;
            g_sh[i + 1] = v1;
        }
    } else {
        for (int i = 2 * tid; i < N; i += 2 * NTHREADS) {
            int t = t0 - HALO + i;
            float s0 = 0.f, s1 = 0.f, s2 = 0.f;
            if (t >= 0 && t + 2 < TT) {
#pragma unroll
                for (int c = 0; c < 8; c++) {
                    float2 x = __ldg((const float2*)(Xb + off[c] + t));
                    s0 += x.x; s1 += x.y;
                    s2 += __ldg(Xb + off[c] + t + 2);
                }
            } else {
                if (t >= 0 && t < TT) {
#pragma unroll
                    for (int c = 0; c < 8; c++) s0 += __ldg(Xb + off[c] + t);
                }
                if (t + 1 >= 0 && t + 1 < TT) {
#pragma unroll
                    for (int c = 0; c < 8; c++) s1 += __ldg(Xb + off[c] + t + 1);
                }
                if (t + 2 >= 0 && t + 2 < TT) {
#pragma unroll
                    for (int c = 0; c < 8; c++) s2 += __ldg(Xb + off[c] + t + 2);
                }
            }
            g_sh[i] = (t >= 0 && t < Te) ? (s1 - s0) : 0.f;
            g_sh[i + 1] = (t + 1 >= 0 && t + 1 < Te) ? (s2 - s1) : 0.f;
        }
    }

    ull wd[8][9];
    load_wd(W, CI, h, wd);
    __syncthreads();

    float am[8] = {0, 0, 0, 0, 0, 0, 0, 0};
    float an[8] = {0, 0, 0, 0, 0, 0, 0, 0};

#pragma unroll 1
    for (int p = 0; p < TILE / (2 * NTHREADS); p++) {
        int q = 2 * tid + p * (2 * NTHREADS);
        int t = t0 + q;
        if (t < Te) {
            float vft = 1.0f;
            float vfu = (t + 1 < Te) ? 1.0f : 0.0f;
            pair_conv<DI>(g_sh, q, wd, am, an, vft, vfu);
        }
    }
    __syncthreads();
    block_write_partial(sw, am, an, CI, b, h, tile);
}

// ============================================================================
// Residue path body: large dilation (di 9..13). Rotation window; 8 warps = 8 h
// per block share the same (b, 32-residue window) so X lines hit L1.
// ============================================================================
template <int DIFF>
__device__ __forceinline__ float gsumT(const float* __restrict__ Xb,
                                       const int off[8], int t) {
    float s = 0.f;
#pragma unroll
    for (int i = 0; i < 8; i++) {
        const float* p = Xb + off[i] + t;
        float x = __ldg(p);
        if (DIFF) x = __ldg(p + 1) - x;
        s += x;
    }
    return s;
}

template <int DI, int DIFF, int U>
__device__ __forceinline__ void residue_step(ull gd[9], const ull w2[4][9],
                                             float am[8], float an[8],
                                             const float* __restrict__ Xb,
                                             const int off[8], int r, int mb, int M) {
    constexpr int D = 1 << DI;
    int m = mb + U;
    if (m < M) {
        conv_step<U>(gd, w2, am, an);
        int sn = m + 5;
        gd[U] = dup2((sn < M) ? gsumT<DIFF>(Xb, off, r + sn * D) : 0.f);
    }
}

template <int DI, int DIFF>
__device__ __forceinline__ void residue_body(int rlin,
                                             const float* __restrict__ X,
                                             const float* __restrict__ W,
                                             const int* __restrict__ idx) {
    constexpr int D = 1 << DI;
    constexpr int NRB32 = 1 << (DI - 5);    // 32-residue windows
    constexpr int CI = 18 + (DI - 9) * 2 + DIFF;
    constexpr int Te = TT - DIFF;

    int rb = rlin % NRB32;
    int hb = (rlin / NRB32) & 3;
    int b = rlin / (NRB32 * 4);
    int lane = threadIdx.x & 31;
    int warp = threadIdx.x >> 5;
    int h = hb * 8 + warp;
    int r = rb * 32 + lane;                 // residue < D
    int M = (Te - r + D - 1) / D;           // strip length >= 1

    int off[8];
    {
        const int* ip = idx + (CI * HH + h) * 8;
#pragma unroll
        for (int i = 0; i < 8; i++) off[i] = ip[i] * TT;
    }
    const float* Xb = X + b * CC * TT;

    ull w2[4][9];
    load_w2(W, CI, h, w2);

    ull gd[9];
#pragma unroll
    for (int j = 0; j < 9; j++) {
        int s = j - 4;
        gd[j] = dup2((s >= 0 && s < M) ? gsumT<DIFF>(Xb, off, r + s * D) : 0.f);
    }

    float am[8] = {0, 0, 0, 0, 0, 0, 0, 0};
    float an[8] = {0, 0, 0, 0, 0, 0, 0, 0};

#pragma unroll 1
    for (int mb = 0; mb < M; mb += 9) {
        residue_step<DI, DIFF, 0>(gd, w2, am, an, Xb, off, r, mb, M);
        residue_step<DI, DIFF, 1>(gd, w2, am, an, Xb, off, r, mb, M);
        residue_step<DI, DIFF, 2>(gd, w2, am, an, Xb, off, r, mb, M);
        residue_step<DI, DIFF, 3>(gd, w2, am, an, Xb, off, r, mb, M);
        residue_step<DI, DIFF, 4>(gd, w2, am, an, Xb, off, r, mb, M);
        residue_step<DI, DIFF, 5>(gd, w2, am, an, Xb, off, r, mb, M);
        residue_step<DI, DIFF, 6>(gd, w2, am, an, Xb, off, r, mb, M);
        residue_step<DI, DIFF, 7>(gd, w2, am, an, Xb, off, r, mb, M);
        residue_step<DI, DIFF, 8>(gd, w2, am, an, Xb, off, r, mb, M);
    }
    warp_write_partial(am, an, CI, b, h, rb);
}

// ============================================================================
// FUSED kernel: tile blocks and residue blocks interleaved 3:2 so every wave
// carries a mix — residue (LDG-latency-bound) warps fill tile (issue-bound)
// stall cycles on the same SM.
// ============================================================================
__global__ void __launch_bounds__(256, 2)
fused_all(const float* __restrict__ X, const float* __restrict__ W,
          const int* __restrict__ idx) {
    __shared__ float g_sh[TILE + 2 * 4 * 256];   // 40KB (tile path only)
    __shared__ float sw[128];

    int bx = blockIdx.x;
    int tile_lin = -1, res_lin = -1;
    if (bx < 38400) {
        int g = bx / 5, r5 = bx % 5;
        if (r5 < 3) tile_lin = g * 3 + r5;        // 0..23039
        else        res_lin = g * 2 + (r5 - 3);   // 0..15359
    } else {
        res_lin = 15360 + (bx - 38400);           // 15360..15871
    }

    if (tile_lin >= 0) {
        int ci = tile_lin / (NTILE * HH * BB);
        int r = tile_lin % (NTILE * HH * BB);
        switch (ci) {
            case 0:  tile_body<0, 0>(r, g_sh, sw, X, W, idx); break;
            case 1:  tile_body<0, 1>(r, g_sh, sw, X, W, idx); break;
            case 2:  tile_body<1, 0>(r, g_sh, sw, X, W, idx); break;
            case 3:  tile_body<1, 1>(r, g_sh, sw, X, W, idx); break;
            case 4:  tile_body<2, 0>(r, g_sh, sw, X, W, idx); break;
            case 5:  tile_body<2, 1>(r, g_sh, sw, X, W, idx); break;
            case 6:  tile_body<3, 0>(r, g_sh, sw, X, W, idx); break;
            case 7:  tile_body<3, 1>(r, g_sh, sw, X, W, idx); break;
            case 8:  tile_body<4, 0>(r, g_sh, sw, X, W, idx); break;
            case 9:  tile_body<4, 1>(r, g_sh, sw, X, W, idx); break;
            case 10: tile_body<5, 0>(r, g_sh, sw, X, W, idx); break;
            case 11: tile_body<5, 1>(r, g_sh, sw, X, W, idx); break;
            case 12: tile_body<6, 0>(r, g_sh, sw, X, W, idx); break;
            case 13: tile_body<6, 1>(r, g_sh, sw, X, W, idx); break;
            case 14: tile_body<7, 0>(r, g_sh, sw, X, W, idx); break;
            case 15: tile_body<7, 1>(r, g_sh, sw, X, W, idx); break;
            case 16: tile_body<8, 0>(r, g_sh, sw, X, W, idx); break;
            case 17: tile_body<8, 1>(r, g_sh, sw, X, W, idx); break;
        }
    } else {
        int bxr = res_lin;
        int lci, r;
        if      (bxr < 256)   { lci = 0; r = bxr; }
        else if (bxr < 512)   { lci = 1; r = bxr - 256; }
        else if (bxr < 1024)  { lci = 2; r = bxr - 512; }
        else if (bxr < 1536)  { lci = 3; r = bxr - 1024; }
        else if (bxr < 2560)  { lci = 4; r = bxr - 1536; }
        else if (bxr < 3584)  { lci = 5; r = bxr - 2560; }
        else if (bxr < 5632)  { lci = 6; r = bxr - 3584; }
        else if (bxr < 7680)  { lci = 7; r = bxr - 5632; }
        else if (bxr < 11776) { lci = 8; r = bxr - 7680; }
        else                  { lci = 9; r = bxr - 11776; }
        switch (lci) {
            case 0: residue_body<9, 0>(r, X, W, idx); break;
            case 1: residue_body<9, 1>(r, X, W, idx); break;
            case 2: residue_body<10, 0>(r, X, W, idx); break;
            case 3: residue_body<10, 1>(r, X, W, idx); break;
            case 4: residue_body<11, 0>(r, X, W, idx); break;
            case 5: residue_body<11, 1>(r, X, W, idx); break;
            case 6: residue_body<12, 0>(r, X, W, idx); break;
            case 7: residue_body<12, 1>(r, X, W, idx); break;
            case 8: residue_body<13, 0>(r, X, W, idx); break;
            case 9: residue_body<13, 1>(r, X, W, idx); break;
        }
    }
}

// ============================================================================
// Deterministic final reduction -> d_out (writes every element)
// ============================================================================
__global__ void reduce_kernel(float* __restrict__ out) {
    int e = blockIdx.x * 256 + threadIdx.x;
    if (e >= BB * 14336) return;
    int b = e / 14336;
    int rem = e % 14336;
    int cig = rem / 512;
    int r2 = rem % 512;
    int which = r2 / 256;
    int hk = r2 % 256;
    int h = hk >> 3, k = hk & 7;
    int np;
    if (cig < 18) np = NTILE;
    else np = 1 << (((cig - 18) >> 1) + 4);   // D/32 windows
    float s = 0.f;
    for (int p = 0; p < np; p++)
        s += g_partial[cig][b][h][p][which * 8 + k];
    out[e] = s;
}

extern "C" void kernel_launch(void* const* d_in, const int* in_sizes, int n_in,
                              void* d_out, int out_size) {
    const float* X = (const float*)d_in[0];
    const float* W = (const float*)d_in[1];
    const int* idx = (const int*)d_in[2];
    float* out = (float*)d_out;

    fused_all<<<NTILEBLK + NRESBLK, NTHREADS>>>(X, W, idx);
    reduce_kernel<<<(BB * 14336 + 255) / 256, 256>>>(out);
}

// round 11
// speedup vs baseline: 1.6469x; 1.6469x over previous
#include <cuda_runtime.h>

#define BB 4
#define CC 17
#define TT 75000
#define HH 32
#define NTHREADS 256
#define TILE 8192
#define NTILE 10          // ceil(75000/8192)
#define MAXPART 256

#define NTILEBLK (18 * NTILE * HH * BB)   // 23040
#define NRESBLK  15872

// Deterministic partial accumulation scratch: [combo 28][b 4][h 32][part 256][16]
__device__ float g_partial[28][4][32][MAXPART][16];

typedef unsigned long long ull;

// ---------------- f32x2 helpers ----------------
__device__ __forceinline__ ull pack2(float a, float b) {
    ull r; asm("mov.b64 %0, {%1, %2};" : "=l"(r) : "f"(a), "f"(b)); return r;
}
__device__ __forceinline__ ull dup2(float a) {
    ull r; asm("mov.b64 %0, {%1, %1};" : "=l"(r) : "f"(a)); return r;
}
__device__ __forceinline__ void mul2(ull& z, ull a, ull b) {
    asm("mul.rn.f32x2 %0, %1, %2;" : "=l"(z) : "l"(a), "l"(b));
}
__device__ __forceinline__ void fma2(ull& z, ull a, ull b) {
    asm("fma.rn.f32x2 %0, %1, %2, %0;" : "+l"(z) : "l"(a), "l"(b));
}
__device__ __forceinline__ void unpack2(ull z, float& lo, float& hi) {
    asm("mov.b64 {%0, %1}, %2;" : "=f"(lo), "=f"(hi) : "l"(z));
}

// ---------------- scalar minmax + bucket ----------------
__device__ __forceinline__ void bucket(const float z[8], float am[8], float an[8],
                                       float vf) {
    float mx = fmaxf(fmaxf(fmaxf(z[0], z[1]), fmaxf(z[2], z[3])),
                     fmaxf(fmaxf(z[4], z[5]), fmaxf(z[6], z[7])));
    float mn = fminf(fminf(fminf(z[0], z[1]), fminf(z[2], z[3])),
                     fminf(fminf(z[4], z[5]), fminf(z[6], z[7])));
#pragma unroll
    for (int k = 0; k < 8; k++) {
        if (z[k] == mx) am[k] += z[k];   // z==0 for invalid pos -> adds 0
        if (z[k] == mn) an[k] += vf;     // masked by validity
    }
}

// k-packed conv step (residue path): gd = 9 dup'd {g,g}, ROT compile-time.
// w2[kk][j] = { w[2kk][j], w[2kk+1][j] }
template <int ROT>
__device__ __forceinline__ void conv_step(const ull gd[9], const ull w2[4][9],
                                          float am[8], float an[8]) {
    ull acc[4];
    {
        ull g2 = gd[ROT % 9];
#pragma unroll
        for (int kk = 0; kk < 4; kk++) mul2(acc[kk], g2, w2[kk][0]);
    }
#pragma unroll
    for (int j = 1; j < 9; j++) {
        ull g2 = gd[(ROT + j) % 9];
#pragma unroll
        for (int kk = 0; kk < 4; kk++) fma2(acc[kk], g2, w2[kk][j]);
    }
    float z[8];
#pragma unroll
    for (int kk = 0; kk < 4; kk++) unpack2(acc[kk], z[2 * kk], z[2 * kk + 1]);
    bucket(z, am, an, 1.0f);
}

// residue-path weights: k-paired
__device__ __forceinline__ void load_w2(const float* __restrict__ W, int ci, int h,
                                        ull w2[4][9]) {
    const float* wp = W + (ci * 256 + h * 8) * 9;
#pragma unroll
    for (int kk = 0; kk < 4; kk++)
#pragma unroll
        for (int j = 0; j < 9; j++)
            w2[kk][j] = pack2(__ldg(wp + (2 * kk) * 9 + j), __ldg(wp + (2 * kk + 1) * 9 + j));
}

// tile-path weights: duplicated {w,w} (positions in SIMD lanes)
__device__ __forceinline__ void load_wd(const float* __restrict__ W, int ci, int h,
                                        ull wd[8][9]) {
    const float* wp = W + (ci * 256 + h * 8) * 9;
#pragma unroll
    for (int k = 0; k < 8; k++)
#pragma unroll
        for (int j = 0; j < 9; j++)
            wd[k][j] = dup2(__ldg(wp + k * 9 + j));
}

__device__ __forceinline__ void block_write_partial(float* sw, float am[8], float an[8],
                                                    int ci, int b, int h, int blk) {
    int tid = threadIdx.x;
    int lane = tid & 31, warp = tid >> 5;
#pragma unroll
    for (int o = 0; o < 16; o++) {
        float v = (o < 8) ? am[o] : an[o - 8];
        v += __shfl_down_sync(0xffffffffu, v, 16);
        v += __shfl_down_sync(0xffffffffu, v, 8);
        v += __shfl_down_sync(0xffffffffu, v, 4);
        v += __shfl_down_sync(0xffffffffu, v, 2);
        v += __shfl_down_sync(0xffffffffu, v, 1);
        if (lane == 0) sw[warp * 16 + o] = v;
    }
    __syncthreads();
    if (tid < 16) {
        float s = 0.f;
#pragma unroll
        for (int wN = 0; wN < 8; wN++) s += sw[wN * 16 + tid];
        g_partial[ci][b][h][blk][tid] = s;
    }
}

// per-warp partial write (residue path, one h per warp)
__device__ __forceinline__ void warp_write_partial(float am[8], float an[8],
                                                   int ci, int b, int h, int part) {
    int lane = threadIdx.x & 31;
#pragma unroll
    for (int o = 0; o < 16; o++) {
        float v = (o < 8) ? am[o] : an[o - 8];
        v += __shfl_down_sync(0xffffffffu, v, 16);
        v += __shfl_down_sync(0xffffffffu, v, 8);
        v += __shfl_down_sync(0xffffffffu, v, 4);
        v += __shfl_down_sync(0xffffffffu, v, 2);
        v += __shfl_down_sync(0xffffffffu, v, 1);
        if (lane == 0) g_partial[ci][b][h][part][o] = v;
    }
}

// ============================================================================
// Position-paired conv, dup'd weights: one aligned LDS.64 {g_t+jD, g_t+jD+1}
// feeds all 8 k-accumulators; acc[k] = {z_t[k], z_u[k]}. No swap MOVs.
// ============================================================================
template <int DI>
__device__ __forceinline__ void pair_conv(const float* __restrict__ g_sh, int q,
                                          const ull wd[8][9],
                                          float am[8], float an[8],
                                          float vft, float vfu) {
    constexpr int D = 1 << DI;
    const ull* gp = (const ull*)g_sh;
    ull acc[8];

    if (DI == 0) {
        // window g[q .. q+9]; aligned pairs P[i] = {g[q+2i], g[q+2i+1]}
        ull P[5];
#pragma unroll
        for (int i = 0; i < 5; i++) P[i] = gp[(q >> 1) + i];
        float lo[5], hi[5];
#pragma unroll
        for (int i = 0; i < 5; i++) unpack2(P[i], lo[i], hi[i]);
#pragma unroll
        for (int j = 0; j < 9; j++) {
            ull v = ((j & 1) == 0) ? P[j >> 1]
                                   : pack2(hi[(j - 1) >> 1], lo[(j + 1) >> 1]);
            if (j == 0) {
#pragma unroll
                for (int k = 0; k < 8; k++) mul2(acc[k], v, wd[k][0]);
            } else {
#pragma unroll
                for (int k = 0; k < 8; k++) fma2(acc[k], v, wd[k][j]);
            }
        }
    } else {
#pragma unroll
        for (int j = 0; j < 9; j++) {
            ull v = gp[(q + j * D) >> 1];    // q even, j*D even -> aligned LDS.64
            if (j == 0) {
#pragma unroll
                for (int k = 0; k < 8; k++) mul2(acc[k], v, wd[k][0]);
            } else {
#pragma unroll
                for (int k = 0; k < 8; k++) fma2(acc[k], v, wd[k][j]);
            }
        }
    }

    float zt[8], zu[8];
#pragma unroll
    for (int k = 0; k < 8; k++) unpack2(acc[k], zt[k], zu[k]);
    bucket(zt, am, an, vft);
    bucket(zu, am, an, vfu);
}

// ============================================================================
// Path A: small dilation (di 0..8). Scalar g tile + position-paired conv.
// ============================================================================
template <int DI, int DIFF>
__device__ __forceinline__ void tile_body(int rlin, float* g_sh, float* sw,
                                          const float* __restrict__ X,
                                          const float* __restrict__ W,
                                          const int* __restrict__ idx) {
    constexpr int D = 1 << DI;
    constexpr int HALO = 4 * D;
    constexpr int N = TILE + 2 * HALO;
    constexpr int CI = DI * 2 + DIFF;
    constexpr int Te = TT - DIFF;

    int tile = rlin % NTILE;
    int h = (rlin / NTILE) % HH;
    int b = rlin / (NTILE * HH);
    int t0 = tile * TILE;
    int tid = threadIdx.x;

    int off[8];
    {
        const int* ip = idx + (CI * HH + h) * 8;
#pragma unroll
        for (int i = 0; i < 8; i++) off[i] = ip[i] * TT;
    }
    const float* Xb = X + b * CC * TT;

    // ---- build g tile (zero padded outside [0, Te)) ----
    if (DIFF == 0) {
        for (int i = 2 * tid; i < N; i += 2 * NTHREADS) {
            int t = t0 - HALO + i;
            float v0 = 0.f, v1 = 0.f;
            if (t >= 0 && t + 1 < TT) {
#pragma unroll
                for (int c = 0; c < 8; c++) {
                    float2 x = __ldg((const float2*)(Xb + off[c] + t));
                    v0 += x.x; v1 += x.y;
                }
            } else {
                if (t >= 0 && t < TT) {
#pragma unroll
                    for (int c = 0; c < 8; c++) v0 += __ldg(Xb + off[c] + t);
                }
                if (t + 1 >= 0 && t + 1 < TT) {
#pragma unroll
                    for (int c = 0; c < 8; c++) v1 += __ldg(Xb + off[c] + t + 1);
                }
            }
            g_sh[i] = v0;
            g_sh[i + 1] = v1;
        }
    } else {
        for (int i = 2 * tid; i < N; i += 2 * NTHREADS) {
            int t = t0 - HALO + i;
            float s0 = 0.f, s1 = 0.f, s2 = 0.f;
            if (t >= 0 && t + 2 < TT) {
#pragma unroll
                for (int c = 0; c < 8; c++) {
                    float2 x = __ldg((const float2*)(Xb + off[c] + t));
                    s0 += x.x; s1 += x.y;
                    s2 += __ldg(Xb + off[c] + t + 2);
                }
            } else {
                if (t >= 0 && t < TT) {
#pragma unroll
                    for (int c = 0; c < 8; c++) s0 += __ldg(Xb + off[c] + t);
                }
                if (t + 1 >= 0 && t + 1 < TT) {
#pragma unroll
                    for (int c = 0; c < 8; c++) s1 += __ldg(Xb + off[c] + t + 1);
                }
                if (t + 2 >= 0 && t + 2 < TT) {
#pragma unroll
                    for (int c = 0; c < 8; c++) s2 += __ldg(Xb + off[c] + t + 2);
                }
            }
            g_sh[i] = (t >= 0 && t < Te) ? (s1 - s0) : 0.f;
            g_sh[i + 1] = (t + 1 >= 0 && t + 1 < Te) ? (s2 - s1) : 0.f;
        }
    }

    ull wd[8][9];
    load_wd(W, CI, h, wd);
    __syncthreads();

    float am[8] = {0, 0, 0, 0, 0, 0, 0, 0};
    float an[8] = {0, 0, 0, 0, 0, 0, 0, 0};

#pragma unroll 1
    for (int p = 0; p < TILE / (2 * NTHREADS); p++) {
        int q = 2 * tid + p * (2 * NTHREADS);
        int t = t0 + q;
        if (t < Te) {
            float vft = 1.0f;
            float vfu = (t + 1 < Te) ? 1.0f : 0.0f;
            pair_conv<DI>(g_sh, q, wd, am, an, vft, vfu);
        }
    }
    __syncthreads();
    block_write_partial(sw, am, an, CI, b, h, tile);
}

__global__ void __launch_bounds__(256, 2)
tile_all(const float* __restrict__ X, const float* __restrict__ W,
         const int* __restrict__ idx) {
    __shared__ float g_sh[TILE + 2 * 4 * 256];   // max N (DI=8): 10240 floats = 40KB
    __shared__ float sw[128];
    int ci = blockIdx.x / (NTILE * HH * BB);
    int r = blockIdx.x % (NTILE * HH * BB);
    switch (ci) {
        case 0:  tile_body<0, 0>(r, g_sh, sw, X, W, idx); break;
        case 1:  tile_body<0, 1>(r, g_sh, sw, X, W, idx); break;
        case 2:  tile_body<1, 0>(r, g_sh, sw, X, W, idx); break;
        case 3:  tile_body<1, 1>(r, g_sh, sw, X, W, idx); break;
        case 4:  tile_body<2, 0>(r, g_sh, sw, X, W, idx); break;
        case 5:  tile_body<2, 1>(r, g_sh, sw, X, W, idx); break;
        case 6:  tile_body<3, 0>(r, g_sh, sw, X, W, idx); break;
        case 7:  tile_body<3, 1>(r, g_sh, sw, X, W, idx); break;
        case 8:  tile_body<4, 0>(r, g_sh, sw, X, W, idx); break;
        case 9:  tile_body<4, 1>(r, g_sh, sw, X, W, idx); break;
        case 10: tile_body<5, 0>(r, g_sh, sw, X, W, idx); break;
        case 11: tile_body<5, 1>(r, g_sh, sw, X, W, idx); break;
        case 12: tile_body<6, 0>(r, g_sh, sw, X, W, idx); break;
        case 13: tile_body<6, 1>(r, g_sh, sw, X, W, idx); break;
        case 14: tile_body<7, 0>(r, g_sh, sw, X, W, idx); break;
        case 15: tile_body<7, 1>(r, g_sh, sw, X, W, idx); break;
        case 16: tile_body<8, 0>(r, g_sh, sw, X, W, idx); break;
        case 17: tile_body<8, 1>(r, g_sh, sw, X, W, idx); break;
    }
}

// ============================================================================
// Path B: large dilation (di 9..13). Residue walk, rotation window,
// h-GROUPED: 8 warps = 8 h per block share the same (b, 32-residue window).
// ============================================================================
template <int DIFF>
__device__ __forceinline__ float gsumT(const float* __restrict__ Xb,
                                       const int off[8], int t) {
    float s = 0.f;
#pragma unroll
    for (int i = 0; i < 8; i++) {
        const float* p = Xb + off[i] + t;
        float x = __ldg(p);
        if (DIFF) x = __ldg(p + 1) - x;
        s += x;
    }
    return s;
}

template <int DI, int DIFF, int U>
__device__ __forceinline__ void residue_step(ull gd[9], const ull w2[4][9],
                                             float am[8], float an[8],
                                             const float* __restrict__ Xb,
                                             const int off[8], int r, int mb, int M) {
    constexpr int D = 1 << DI;
    int m = mb + U;
    if (m < M) {
        conv_step<U>(gd, w2, am, an);
        int sn = m + 5;
        gd[U] = dup2((sn < M) ? gsumT<DIFF>(Xb, off, r + sn * D) : 0.f);
    }
}

template <int DI, int DIFF>
__device__ __forceinline__ void residue_body(int rlin,
                                             const float* __restrict__ X,
                                             const float* __restrict__ W,
                                             const int* __restrict__ idx) {
    constexpr int D = 1 << DI;
    constexpr int NRB32 = 1 << (DI - 5);    // 32-residue windows
    constexpr int CI = 18 + (DI - 9) * 2 + DIFF;
    constexpr int Te = TT - DIFF;

    int rb = rlin % NRB32;
    int hb = (rlin / NRB32) & 3;
    int b = rlin / (NRB32 * 4);
    int lane = threadIdx.x & 31;
    int warp = threadIdx.x >> 5;
    int h = hb * 8 + warp;
    int r = rb * 32 + lane;                 // residue < D
    int M = (Te - r + D - 1) / D;           // strip length >= 1

    int off[8];
    {
        const int* ip = idx + (CI * HH + h) * 8;
#pragma unroll
        for (int i = 0; i < 8; i++) off[i] = ip[i] * TT;
    }
    const float* Xb = X + b * CC * TT;

    ull w2[4][9];
    load_w2(W, CI, h, w2);

    ull gd[9];
#pragma unroll
    for (int j = 0; j < 9; j++) {
        int s = j - 4;
        gd[j] = dup2((s >= 0 && s < M) ? gsumT<DIFF>(Xb, off, r + s * D) : 0.f);
    }

    float am[8] = {0, 0, 0, 0, 0, 0, 0, 0};
    float an[8] = {0, 0, 0, 0, 0, 0, 0, 0};

#pragma unroll 1
    for (int mb = 0; mb < M; mb += 9) {
        residue_step<DI, DIFF, 0>(gd, w2, am, an, Xb, off, r, mb, M);
        residue_step<DI, DIFF, 1>(gd, w2, am, an, Xb, off, r, mb, M);
        residue_step<DI, DIFF, 2>(gd, w2, am, an, Xb, off, r, mb, M);
        residue_step<DI, DIFF, 3>(gd, w2, am, an, Xb, off, r, mb, M);
        residue_step<DI, DIFF, 4>(gd, w2, am, an, Xb, off, r, mb, M);
        residue_step<DI, DIFF, 5>(gd, w2, am, an, Xb, off, r, mb, M);
        residue_step<DI, DIFF, 6>(gd, w2, am, an, Xb, off, r, mb, M);
        residue_step<DI, DIFF, 7>(gd, w2, am, an, Xb, off, r, mb, M);
        residue_step<DI, DIFF, 8>(gd, w2, am, an, Xb, off, r, mb, M);
    }
    warp_write_partial(am, an, CI, b, h, rb);
}

__global__ void __launch_bounds__(256, 2)
residue_all(const float* __restrict__ X, const float* __restrict__ W,
            const int* __restrict__ idx) {
    int bx = blockIdx.x;
    int lci, r;
    if      (bx < 256)   { lci = 0; r = bx; }
    else if (bx < 512)   { lci = 1; r = bx - 256; }
    else if (bx < 1024)  { lci = 2; r = bx - 512; }
    else if (bx < 1536)  { lci = 3; r = bx - 1024; }
    else if (bx < 2560)  { lci = 4; r = bx - 1536; }
    else if (bx < 3584)  { lci = 5; r = bx - 2560; }
    else if (bx < 5632)  { lci = 6; r = bx - 3584; }
    else if (bx < 7680)  { lci = 7; r = bx - 5632; }
    else if (bx < 11776) { lci = 8; r = bx - 7680; }
    else                 { lci = 9; r = bx - 11776; }
    switch (lci) {
        case 0: residue_body<9, 0>(r, X, W, idx); break;
        case 1: residue_body<9, 1>(r, X, W, idx); break;
        case 2: residue_body<10, 0>(r, X, W, idx); break;
        case 3: residue_body<10, 1>(r, X, W, idx); break;
        case 4: residue_body<11, 0>(r, X, W, idx); break;
        case 5: residue_body<11, 1>(r, X, W, idx); break;
        case 6: residue_body<12, 0>(r, X, W, idx); break;
        case 7: residue_body<12, 1>(r, X, W, idx); break;
        case 8: residue_body<13, 0>(r, X, W, idx); break;
        case 9: residue_body<13, 1>(r, X, W, idx); break;
    }
}

// ============================================================================
// Deterministic final reduction -> d_out (writes every element)
// ============================================================================
__global__ void reduce_kernel(float* __restrict__ out) {
    int e = blockIdx.x * 256 + threadIdx.x;
    if (e >= BB * 14336) return;
    int b = e / 14336;
    int rem = e % 14336;
    int cig = rem / 512;
    int r2 = rem % 512;
    int which = r2 / 256;
    int hk = r2 % 256;
    int h = hk >> 3, k = hk & 7;
    int np;
    if (cig < 18) np = NTILE;
    else np = 1 << (((cig - 18) >> 1) + 4);   // D/32 windows
    float s = 0.f;
    for (int p = 0; p < np; p++)
        s += g_partial[cig][b][h][p][which * 8 + k];
    out[e] = s;
}

extern "C" void kernel_launch(void* const* d_in, const int* in_sizes, int n_in,
                              void* d_out, int out_size) {
    const float* X = (const float*)d_in[0];
    const float* W = (const float*)d_in[1];
    const int* idx = (const int*)d_in[2];
    float* out = (float*)d_out;

    // Fork-join across two streams so tile_all (issue-bound) and residue_all
    // (LDG-latency-bound) co-reside on the SMs. cudaStreamPerThread is a
    // built-in handle (no stream creation); events are host-side, timing-
    // disabled, and intentionally not destroyed mid-capture.
    cudaEvent_t e_fork, e_join;
    cudaEventCreateWithFlags(&e_fork, cudaEventDisableTiming);
    cudaEventCreateWithFlags(&e_join, cudaEventDisableTiming);

    cudaEventRecord(e_fork, 0);
    cudaStreamWaitEvent(cudaStreamPerThread, e_fork, 0);

    residue_all<<<NRESBLK, NTHREADS, 0, cudaStreamPerThread>>>(X, W, idx);
    tile_all<<<NTILEBLK, NTHREADS>>>(X, W, idx);

    cudaEventRecord(e_join, cudaStreamPerThread);
    cudaStreamWaitEvent(0, e_join, 0);

    reduce_kernel<<<(BB * 14336 + 255) / 256, 256>>>(out);
}

// round 12
// speedup vs baseline: 1.6909x; 1.0267x over previous
#include <cuda_runtime.h>

#define BB 4
#define CC 17
#define TT 75000
#define HH 32
#define NTHREADS 256
#define TILE 8192
#define NTILE 10          // ceil(75000/8192)
#define MAXPART 256

#define NTILEBLK (18 * NTILE * HH * BB)   // 23040
#define NRESBLK  15872

// Deterministic partial accumulation scratch: [combo 28][b 4][h 32][part 256][16]
__device__ float g_partial[28][4][32][MAXPART][16];
// Precomputed diff(X): same layout as X
__device__ float g_dX[BB * CC * TT];

typedef unsigned long long ull;

// ---------------- f32x2 helpers ----------------
__device__ __forceinline__ ull pack2(float a, float b) {
    ull r; asm("mov.b64 %0, {%1, %2};" : "=l"(r) : "f"(a), "f"(b)); return r;
}
__device__ __forceinline__ ull dup2(float a) {
    ull r; asm("mov.b64 %0, {%1, %1};" : "=l"(r) : "f"(a)); return r;
}
__device__ __forceinline__ void mul2(ull& z, ull a, ull b) {
    asm("mul.rn.f32x2 %0, %1, %2;" : "=l"(z) : "l"(a), "l"(b));
}
__device__ __forceinline__ void fma2(ull& z, ull a, ull b) {
    asm("fma.rn.f32x2 %0, %1, %2, %0;" : "+l"(z) : "l"(a), "l"(b));
}
__device__ __forceinline__ void unpack2(ull z, float& lo, float& hi) {
    asm("mov.b64 {%0, %1}, %2;" : "=f"(lo), "=f"(hi) : "l"(z));
}

// ---------------- scalar minmax + bucket ----------------
__device__ __forceinline__ void bucket(const float z[8], float am[8], float an[8],
                                       float vf) {
    float mx = fmaxf(fmaxf(fmaxf(z[0], z[1]), fmaxf(z[2], z[3])),
                     fmaxf(fmaxf(z[4], z[5]), fmaxf(z[6], z[7])));
    float mn = fminf(fminf(fminf(z[0], z[1]), fminf(z[2], z[3])),
                     fminf(fminf(z[4], z[5]), fminf(z[6], z[7])));
#pragma unroll
    for (int k = 0; k < 8; k++) {
        if (z[k] == mx) am[k] += z[k];   // z==0 for invalid pos -> adds 0
        if (z[k] == mn) an[k] += vf;     // masked by validity
    }
}

// k-packed conv step (residue path): gd = 9 dup'd {g,g}, ROT compile-time.
// w2[kk][j] = { w[2kk][j], w[2kk+1][j] }
template <int ROT>
__device__ __forceinline__ void conv_step(const ull gd[9], const ull w2[4][9],
                                          float am[8], float an[8]) {
    ull acc[4];
    {
        ull g2 = gd[ROT % 9];
#pragma unroll
        for (int kk = 0; kk < 4; kk++) mul2(acc[kk], g2, w2[kk][0]);
    }
#pragma unroll
    for (int j = 1; j < 9; j++) {
        ull g2 = gd[(ROT + j) % 9];
#pragma unroll
        for (int kk = 0; kk < 4; kk++) fma2(acc[kk], g2, w2[kk][j]);
    }
    float z[8];
#pragma unroll
    for (int kk = 0; kk < 4; kk++) unpack2(acc[kk], z[2 * kk], z[2 * kk + 1]);
    bucket(z, am, an, 1.0f);
}

// residue-path weights: k-paired
__device__ __forceinline__ void load_w2(const float* __restrict__ W, int ci, int h,
                                        ull w2[4][9]) {
    const float* wp = W + (ci * 256 + h * 8) * 9;
#pragma unroll
    for (int kk = 0; kk < 4; kk++)
#pragma unroll
        for (int j = 0; j < 9; j++)
            w2[kk][j] = pack2(__ldg(wp + (2 * kk) * 9 + j), __ldg(wp + (2 * kk + 1) * 9 + j));
}

// tile-path weights: duplicated {w,w} (positions in SIMD lanes)
__device__ __forceinline__ void load_wd(const float* __restrict__ W, int ci, int h,
                                        ull wd[8][9]) {
    const float* wp = W + (ci * 256 + h * 8) * 9;
#pragma unroll
    for (int k = 0; k < 8; k++)
#pragma unroll
        for (int j = 0; j < 9; j++)
            wd[k][j] = dup2(__ldg(wp + k * 9 + j));
}

__device__ __forceinline__ void block_write_partial(float* sw, float am[8], float an[8],
                                                    int ci, int b, int h, int blk) {
    int tid = threadIdx.x;
    int lane = tid & 31, warp = tid >> 5;
#pragma unroll
    for (int o = 0; o < 16; o++) {
        float v = (o < 8) ? am[o] : an[o - 8];
        v += __shfl_down_sync(0xffffffffu, v, 16);
        v += __shfl_down_sync(0xffffffffu, v, 8);
        v += __shfl_down_sync(0xffffffffu, v, 4);
        v += __shfl_down_sync(0xffffffffu, v, 2);
        v += __shfl_down_sync(0xffffffffu, v, 1);
        if (lane == 0) sw[warp * 16 + o] = v;
    }
    __syncthreads();
    if (tid < 16) {
        float s = 0.f;
#pragma unroll
        for (int wN = 0; wN < 8; wN++) s += sw[wN * 16 + tid];
        g_partial[ci][b][h][blk][tid] = s;
    }
}

// per-warp partial write (residue path, one h per warp)
__device__ __forceinline__ void warp_write_partial(float am[8], float an[8],
                                                   int ci, int b, int h, int part) {
    int lane = threadIdx.x & 31;
#pragma unroll
    for (int o = 0; o < 16; o++) {
        float v = (o < 8) ? am[o] : an[o - 8];
        v += __shfl_down_sync(0xffffffffu, v, 16);
        v += __shfl_down_sync(0xffffffffu, v, 8);
        v += __shfl_down_sync(0xffffffffu, v, 4);
        v += __shfl_down_sync(0xffffffffu, v, 2);
        v += __shfl_down_sync(0xffffffffu, v, 1);
        if (lane == 0) g_partial[ci][b][h][part][o] = v;
    }
}

// ============================================================================
// diff(X) precompute: dX[b][c][t] = X[b][c][t+1] - X[b][c][t], last elem 0.
// ============================================================================
__global__ void diff_kernel(const float* __restrict__ X) {
    int e = blockIdx.x * 256 + threadIdx.x;
    if (e >= BB * CC * TT) return;
    int t = e % TT;
    float v = 0.f;
    if (t < TT - 1) v = __ldg(X + e + 1) - __ldg(X + e);
    g_dX[e] = v;
}

// ============================================================================
// Position-paired conv, dup'd weights: one aligned LDS.64 {g_t+jD, g_t+jD+1}
// feeds all 8 k-accumulators; acc[k] = {z_t[k], z_u[k]}. No swap MOVs.
// ============================================================================
template <int DI>
__device__ __forceinline__ void pair_conv(const float* __restrict__ g_sh, int q,
                                          const ull wd[8][9],
                                          float am[8], float an[8],
                                          float vft, float vfu) {
    constexpr int D = 1 << DI;
    const ull* gp = (const ull*)g_sh;
    ull acc[8];

    if (DI == 0) {
        // window g[q .. q+9]; aligned pairs P[i] = {g[q+2i], g[q+2i+1]}
        ull P[5];
#pragma unroll
        for (int i = 0; i < 5; i++) P[i] = gp[(q >> 1) + i];
        float lo[5], hi[5];
#pragma unroll
        for (int i = 0; i < 5; i++) unpack2(P[i], lo[i], hi[i]);
#pragma unroll
        for (int j = 0; j < 9; j++) {
            ull v = ((j & 1) == 0) ? P[j >> 1]
                                   : pack2(hi[(j - 1) >> 1], lo[(j + 1) >> 1]);
            if (j == 0) {
#pragma unroll
                for (int k = 0; k < 8; k++) mul2(acc[k], v, wd[k][0]);
            } else {
#pragma unroll
                for (int k = 0; k < 8; k++) fma2(acc[k], v, wd[k][j]);
            }
        }
    } else {
#pragma unroll
        for (int j = 0; j < 9; j++) {
            ull v = gp[(q + j * D) >> 1];    // q even, j*D even -> aligned LDS.64
            if (j == 0) {
#pragma unroll
                for (int k = 0; k < 8; k++) mul2(acc[k], v, wd[k][0]);
            } else {
#pragma unroll
                for (int k = 0; k < 8; k++) fma2(acc[k], v, wd[k][j]);
            }
        }
    }

    float zt[8], zu[8];
#pragma unroll
    for (int k = 0; k < 8; k++) unpack2(acc[k], zt[k], zu[k]);
    bucket(zt, am, an, vft);
    bucket(zu, am, an, vfu);
}

// ============================================================================
// Path A: small dilation (di 0..8). Unified build from src (= X or dX).
// ============================================================================
template <int DI, int DIFF>
__device__ __forceinline__ void tile_body(int rlin, float* g_sh, float* sw,
                                          const float* __restrict__ X,
                                          const float* __restrict__ W,
                                          const int* __restrict__ idx) {
    constexpr int D = 1 << DI;
    constexpr int HALO = 4 * D;
    constexpr int N = TILE + 2 * HALO;
    constexpr int CI = DI * 2 + DIFF;
    constexpr int Te = TT - DIFF;

    int tile = rlin % NTILE;
    int h = (rlin / NTILE) % HH;
    int b = rlin / (NTILE * HH);
    int t0 = tile * TILE;
    int tid = threadIdx.x;

    int off[8];
    {
        const int* ip = idx + (CI * HH + h) * 8;
#pragma unroll
        for (int i = 0; i < 8; i++) off[i] = ip[i] * TT;
    }
    const float* srcb = (DIFF ? (const float*)g_dX : X) + b * CC * TT;

    // ---- build g tile (zero padded outside [0, Te)) ----
    for (int i = 2 * tid; i < N; i += 2 * NTHREADS) {
        int t = t0 - HALO + i;
        float v0 = 0.f, v1 = 0.f;
        if (t >= 0 && t + 1 < Te) {
#pragma unroll
            for (int c = 0; c < 8; c++) {
                float2 x = __ldg((const float2*)(srcb + off[c] + t));
                v0 += x.x; v1 += x.y;
            }
        } else {
            if (t >= 0 && t < Te) {
#pragma unroll
                for (int c = 0; c < 8; c++) v0 += __ldg(srcb + off[c] + t);
            }
            if (t + 1 >= 0 && t + 1 < Te) {
#pragma unroll
                for (int c = 0; c < 8; c++) v1 += __ldg(srcb + off[c] + t + 1);
            }
        }
        g_sh[i] = v0;
        g_sh[i + 1] = v1;
    }

    ull wd[8][9];
    load_wd(W, CI, h, wd);
    __syncthreads();

    float am[8] = {0, 0, 0, 0, 0, 0, 0, 0};
    float an[8] = {0, 0, 0, 0, 0, 0, 0, 0};

#pragma unroll 1
    for (int p = 0; p < TILE / (2 * NTHREADS); p++) {
        int q = 2 * tid + p * (2 * NTHREADS);
        int t = t0 + q;
        if (t < Te) {
            float vft = 1.0f;
            float vfu = (t + 1 < Te) ? 1.0f : 0.0f;
            pair_conv<DI>(g_sh, q, wd, am, an, vft, vfu);
        }
    }
    __syncthreads();
    block_write_partial(sw, am, an, CI, b, h, tile);
}

__global__ void __launch_bounds__(256, 2)
tile_all(const float* __restrict__ X, const float* __restrict__ W,
         const int* __restrict__ idx) {
    __shared__ float g_sh[TILE + 2 * 4 * 256];   // max N (DI=8): 10240 floats = 40KB
    __shared__ float sw[128];
    int ci = blockIdx.x / (NTILE * HH * BB);
    int r = blockIdx.x % (NTILE * HH * BB);
    switch (ci) {
        case 0:  tile_body<0, 0>(r, g_sh, sw, X, W, idx); break;
        case 1:  tile_body<0, 1>(r, g_sh, sw, X, W, idx); break;
        case 2:  tile_body<1, 0>(r, g_sh, sw, X, W, idx); break;
        case 3:  tile_body<1, 1>(r, g_sh, sw, X, W, idx); break;
        case 4:  tile_body<2, 0>(r, g_sh, sw, X, W, idx); break;
        case 5:  tile_body<2, 1>(r, g_sh, sw, X, W, idx); break;
        case 6:  tile_body<3, 0>(r, g_sh, sw, X, W, idx); break;
        case 7:  tile_body<3, 1>(r, g_sh, sw, X, W, idx); break;
        case 8:  tile_body<4, 0>(r, g_sh, sw, X, W, idx); break;
        case 9:  tile_body<4, 1>(r, g_sh, sw, X, W, idx); break;
        case 10: tile_body<5, 0>(r, g_sh, sw, X, W, idx); break;
        case 11: tile_body<5, 1>(r, g_sh, sw, X, W, idx); break;
        case 12: tile_body<6, 0>(r, g_sh, sw, X, W, idx); break;
        case 13: tile_body<6, 1>(r, g_sh, sw, X, W, idx); break;
        case 14: tile_body<7, 0>(r, g_sh, sw, X, W, idx); break;
        case 15: tile_body<7, 1>(r, g_sh, sw, X, W, idx); break;
        case 16: tile_body<8, 0>(r, g_sh, sw, X, W, idx); break;
        case 17: tile_body<8, 1>(r, g_sh, sw, X, W, idx); break;
    }
}

// ============================================================================
// Path B: large dilation (di 9..13). Residue walk, rotation window,
// h-GROUPED: 8 warps = 8 h per block share the same (b, 32-residue window).
// DIFF=1 now reads precomputed dX: 8 LDG per slide, same as DIFF=0.
// ============================================================================
__device__ __forceinline__ float gsum8(const float* __restrict__ srcb,
                                       const int off[8], int t) {
    float s = 0.f;
#pragma unroll
    for (int i = 0; i < 8; i++) s += __ldg(srcb + off[i] + t);
    return s;
}

template <int DI, int U>
__device__ __forceinline__ void residue_step(ull gd[9], const ull w2[4][9],
                                             float am[8], float an[8],
                                             const float* __restrict__ srcb,
                                             const int off[8], int r, int mb, int M) {
    constexpr int D = 1 << DI;
    int m = mb + U;
    if (m < M) {
        conv_step<U>(gd, w2, am, an);
        int sn = m + 5;
        gd[U] = dup2((sn < M) ? gsum8(srcb, off, r + sn * D) : 0.f);
    }
}

template <int DI, int DIFF>
__device__ __forceinline__ void residue_body(int rlin,
                                             const float* __restrict__ X,
                                             const float* __restrict__ W,
                                             const int* __restrict__ idx) {
    constexpr int D = 1 << DI;
    constexpr int NRB32 = 1 << (DI - 5);    // 32-residue windows
    constexpr int CI = 18 + (DI - 9) * 2 + DIFF;
    constexpr int Te = TT - DIFF;

    int rb = rlin % NRB32;
    int hb = (rlin / NRB32) & 3;
    int b = rlin / (NRB32 * 4);
    int lane = threadIdx.x & 31;
    int warp = threadIdx.x >> 5;
    int h = hb * 8 + warp;
    int r = rb * 32 + lane;                 // residue < D
    int M = (Te - r + D - 1) / D;           // strip length >= 1

    int off[8];
    {
        const int* ip = idx + (CI * HH + h) * 8;
#pragma unroll
        for (int i = 0; i < 8; i++) off[i] = ip[i] * TT;
    }
    const float* srcb = (DIFF ? (const float*)g_dX : X) + b * CC * TT;

    ull w2[4][9];
    load_w2(W, CI, h, w2);

    ull gd[9];
#pragma unroll
    for (int j = 0; j < 9; j++) {
        int s = j - 4;
        gd[j] = dup2((s >= 0 && s < M) ? gsum8(srcb, off, r + s * D) : 0.f);
    }

    float am[8] = {0, 0, 0, 0, 0, 0, 0, 0};
    float an[8] = {0, 0, 0, 0, 0, 0, 0, 0};

#pragma unroll 1
    for (int mb = 0; mb < M; mb += 9) {
        residue_step<DI, 0>(gd, w2, am, an, srcb, off, r, mb, M);
        residue_step<DI, 1>(gd, w2, am, an, srcb, off, r, mb, M);
        residue_step<DI, 2>(gd, w2, am, an, srcb, off, r, mb, M);
        residue_step<DI, 3>(gd, w2, am, an, srcb, off, r, mb, M);
        residue_step<DI, 4>(gd, w2, am, an, srcb, off, r, mb, M);
        residue_step<DI, 5>(gd, w2, am, an, srcb, off, r, mb, M);
        residue_step<DI, 6>(gd, w2, am, an, srcb, off, r, mb, M);
        residue_step<DI, 7>(gd, w2, am, an, srcb, off, r, mb, M);
        residue_step<DI, 8>(gd, w2, am, an, srcb, off, r, mb, M);
    }
    warp_write_partial(am, an, CI, b, h, rb);
}

__global__ void __launch_bounds__(256, 2)
residue_all(const float* __restrict__ X, const float* __restrict__ W,
            const int* __restrict__ idx) {
    int bx = blockIdx.x;
    int lci, r;
    if      (bx < 256)   { lci = 0; r = bx; }
    else if (bx < 512)   { lci = 1; r = bx - 256; }
    else if (bx < 1024)  { lci = 2; r = bx - 512; }
    else if (bx < 1536)  { lci = 3; r = bx - 1024; }
    else if (bx < 2560)  { lci = 4; r = bx - 1536; }
    else if (bx < 3584)  { lci = 5; r = bx - 2560; }
    else if (bx < 5632)  { lci = 6; r = bx - 3584; }
    else if (bx < 7680)  { lci = 7; r = bx - 5632; }
    else if (bx < 11776) { lci = 8; r = bx - 7680; }
    else                 { lci = 9; r = bx - 11776; }
    switch (lci) {
        case 0: residue_body<9, 0>(r, X, W, idx); break;
        case 1: residue_body<9, 1>(r, X, W, idx); break;
        case 2: residue_body<10, 0>(r, X, W, idx); break;
        case 3: residue_body<10, 1>(r, X, W, idx); break;
        case 4: residue_body<11, 0>(r, X, W, idx); break;
        case 5: residue_body<11, 1>(r, X, W, idx); break;
        case 6: residue_body<12, 0>(r, X, W, idx); break;
        case 7: residue_body<12, 1>(r, X, W, idx); break;
        case 8: residue_body<13, 0>(r, X, W, idx); break;
        case 9: residue_body<13, 1>(r, X, W, idx); break;
    }
}

// ============================================================================
// Deterministic final reduction -> d_out (writes every element)
// ============================================================================
__global__ void reduce_kernel(float* __restrict__ out) {
    int e = blockIdx.x * 256 + threadIdx.x;
    if (e >= BB * 14336) return;
    int b = e / 14336;
    int rem = e % 14336;
    int cig = rem / 512;
    int r2 = rem % 512;
    int which = r2 / 256;
    int hk = r2 % 256;
    int h = hk >> 3, k = hk & 7;
    int np;
    if (cig < 18) np = NTILE;
    else np = 1 << (((cig - 18) >> 1) + 4);   // D/32 windows
    float s = 0.f;
    for (int p = 0; p < np; p++)
        s += g_partial[cig][b][h][p][which * 8 + k];
    out[e] = s;
}

extern "C" void kernel_launch(void* const* d_in, const int* in_sizes, int n_in,
                              void* d_out, int out_size) {
    const float* X = (const float*)d_in[0];
    const float* W = (const float*)d_in[1];
    const int* idx = (const int*)d_in[2];
    float* out = (float*)d_out;

    // diff(X) precompute on stream 0, then fork residue/tile, join, reduce.
    diff_kernel<<<(BB * CC * TT + 255) / 256, 256>>>(X);

    cudaEvent_t e_fork, e_join;
    cudaEventCreateWithFlags(&e_fork, cudaEventDisableTiming);
    cudaEventCreateWithFlags(&e_join, cudaEventDisableTiming);

    cudaEventRecord(e_fork, 0);
    cudaStreamWaitEvent(cudaStreamPerThread, e_fork, 0);

    residue_all<<<NRESBLK, NTHREADS, 0, cudaStreamPerThread>>>(X, W, idx);
    tile_all<<<NTILEBLK, NTHREADS>>>(X, W, idx);

    cudaEventRecord(e_join, cudaStreamPerThread);
    cudaStreamWaitEvent(0, e_join, 0);

    reduce_kernel<<<(BB * 14336 + 255) / 256, 256>>>(out);
}